// round 5
// baseline (speedup 1.0000x reference)
#include <cuda_runtime.h>

#define NC    21
#define HW    (512 * 512)
#define NB    16
#define BHW   (NB * HW)
#define NBINS (NC * NC)
#define QPI   (HW / 4)          /* quads per image = 65536 */

// Zero at module load; the electing last block resets both after use so every
// launch (correctness run, capture, every graph replay) starts clean.
__device__ unsigned int g_conf[NBINS];
__device__ unsigned int g_done;

__global__ void __launch_bounds__(256)
fused_kernel(const float* __restrict__ logits, const int* __restrict__ target,
             float* __restrict__ out) {
    __shared__ unsigned int s_conf[NBINS];
    __shared__ bool s_last;
    for (int i = threadIdx.x; i < NBINS; i += 256) s_conf[i] = 0u;
    __syncthreads();

    const int nquads = BHW / 4;  // 1,048,576
    for (int q = blockIdx.x * 256 + threadIdx.x; q < nquads;
         q += gridDim.x * 256) {
        int b = q >> 16;               // q / QPI  (QPI = 65536)
        int s = (q - (b << 16)) << 2;  // pixel offset within image
        const float4* base =
            (const float4*)(logits + (size_t)b * NC * HW + s);

        int4 t = __ldcs((const int4*)(target + (q << 2)));  // 16B-aligned

        float4 v = __ldcs(base);
        float m0 = v.x, m1 = v.y, m2 = v.z, m3 = v.w;
        int a0 = 0, a1 = 0, a2 = 0, a3 = 0;
        #pragma unroll
        for (int c = 1; c < NC; c++) {
            float4 u = __ldcs(base + (size_t)c * QPI);
            if (u.x > m0) { m0 = u.x; a0 = c; }
            if (u.y > m1) { m1 = u.y; a1 = c; }
            if (u.z > m2) { m2 = u.z; a2 = c; }
            if (u.w > m3) { m3 = u.w; a3 = c; }
        }

        atomicAdd(&s_conf[t.x * NC + a0], 1u);
        atomicAdd(&s_conf[t.y * NC + a1], 1u);
        atomicAdd(&s_conf[t.z * NC + a2], 1u);
        atomicAdd(&s_conf[t.w * NC + a3], 1u);
    }

    __syncthreads();
    for (int i = threadIdx.x; i < NBINS; i += 256) {
        unsigned int v = s_conf[i];
        if (v) atomicAdd(&g_conf[i], v);
    }

    // Make this block's flush globally visible, then elect the last block.
    __threadfence();
    __syncthreads();
    if (threadIdx.x == 0) {
        unsigned int n = atomicAdd(&g_done, 1u);
        s_last = (n == gridDim.x - 1);
    }
    __syncthreads();
    if (!s_last) return;

    // ---- last block: loss epilogue + state reset ----
    int i = threadIdx.x;
    for (int k = i; k < NBINS; k += 256) {
        s_conf[k] = g_conf[k];   // snapshot (all flushes visible: fence+atomic)
    }
    __syncthreads();
    for (int k = i; k < NBINS; k += 256) g_conf[k] = 0u;   // reset for next run
    if (i == 0) g_done = 0u;

    float acc = 0.0f;
    if (i < NC) {
        float tp = (float)s_conf[i * NC + i];
        float rowsum = 0.0f, colsum = 0.0f;
        #pragma unroll
        for (int j = 0; j < NC; j++) {
            rowsum += (float)s_conf[i * NC + j];
            colsum += (float)s_conf[j * NC + i];
        }
        float fp = rowsum - tp;
        float fn = colsum - tp;
        float tn = (float)BHW - tp - fp - fn;
        float sens = (tp + 1.0f) / (tp + fn + 1.0f);
        float spec = (tn + 1.0f) / (tn + fp + 1.0f);
        acc = 0.5f * sens + 0.5f * spec;
    }
    if (i < 32) {   // classes 0..20 all live in warp 0
        #pragma unroll
        for (int off = 16; off > 0; off >>= 1)
            acc += __shfl_down_sync(0xffffffffu, acc, off);
        if (i == 0) out[0] = 1.0f - acc / (float)NC;
    }
}

extern "C" void kernel_launch(void* const* d_in, const int* in_sizes, int n_in,
                              void* d_out, int out_size) {
    const float* logits = (const float*)d_in[0];
    const int* target   = (const int*)d_in[1];
    float* out = (float*)d_out;

    // 1184 = 148 SMs x 8 resident 256-thread blocks: exactly one wave.
    fused_kernel<<<1184, 256>>>(logits, target, out);
}